// round 1
// baseline (speedup 1.0000x reference)
#include <cuda_runtime.h>
#include <math.h>

// ---------------------------------------------------------------------------
// BCEDecorrelatedLoss: bce_mean + 0.1 * distance_corr(outputs, event, w_norm)
//
// Decomposition (all exact, no O(N^2) storage):
//   w_j     = weights_j * N / sum(weights)
//   asum[i] = sum_j |x_i - x_j| * w_j          (x = outputs)
//   bsum[i] = sum_j |y_i - y_j| * w_j          (y = event)
//   a0      = sum_i asum[i]*w_i / N^2 ;  b0 likewise
//   A_ij    = |x_i-x_j| - asum[i]/N - asum[j]/N + a0
//   S_AB    = sum_ij w_i w_j A_ij B_ij   (and S_AA, S_BB)
//   disco   = S_AB / sqrt(S_AA * S_BB)         (N^2 factors cancel)
// ---------------------------------------------------------------------------

#define MAXN 8192

__device__ float g_w[MAXN];
__device__ float g_asum[MAXN];
__device__ float g_bsum[MAXN];
__device__ float g_bce;
__device__ float g_a0, g_b0;
__device__ float g_sab, g_saa, g_sbb;

// Block-wide sum, result broadcast to all threads. Safe to call repeatedly.
__device__ __forceinline__ float blockReduceSum(float v) {
    __shared__ float s[32];
    int lane = threadIdx.x & 31;
    int wid  = threadIdx.x >> 5;
    #pragma unroll
    for (int o = 16; o; o >>= 1) v += __shfl_down_sync(0xffffffffu, v, o);
    if (lane == 0) s[wid] = v;
    __syncthreads();
    int nw = blockDim.x >> 5;
    float r = (threadIdx.x < nw) ? s[threadIdx.x] : 0.0f;
    if (wid == 0) {
        #pragma unroll
        for (int o = 16; o; o >>= 1) r += __shfl_down_sync(0xffffffffu, r, o);
        if (lane == 0) s[0] = r;
    }
    __syncthreads();
    float out = s[0];
    __syncthreads();   // protect s[] for a subsequent call
    return out;
}

// ---------------------------------------------------------------------------
// Kernel A (1 block, 1024 thr): zero accumulators, sum(weights), BCE mean,
// and write normalized weights g_w.
// ---------------------------------------------------------------------------
__global__ void kA(const float* __restrict__ outputs,
                   const float* __restrict__ labels,
                   const float* __restrict__ weights, int n) {
    int tid = threadIdx.x;
    if (tid == 0) { g_sab = 0.0f; g_saa = 0.0f; g_sbb = 0.0f; }
    for (int i = tid; i < n; i += blockDim.x) { g_asum[i] = 0.0f; g_bsum[i] = 0.0f; }

    float sw = 0.0f, sb = 0.0f;
    for (int i = tid; i < n; i += blockDim.x) {
        float x = outputs[i], y = labels[i], w = weights[i];
        sw += w;
        // stable softplus: logaddexp(0, x)
        float sp = fmaxf(x, 0.0f) + log1pf(expf(-fabsf(x)));
        sb += (sp - x * y) * w;
    }
    float swt = blockReduceSum(sw);
    float sbt = blockReduceSum(sb);

    float scale = (float)n / swt;
    for (int i = tid; i < n; i += blockDim.x) g_w[i] = weights[i] * scale;
    if (tid == 0) g_bce = sbt / (float)n;
}

// ---------------------------------------------------------------------------
// Kernel B: pass 1, row sums asum/bsum.  grid (n/TB, n/JT), TB threads.
// ---------------------------------------------------------------------------
#define TB 256
#define JT 1024
__global__ void kB(const float* __restrict__ x, const float* __restrict__ y, int n) {
    __shared__ float sx[JT], sy[JT], sw[JT];
    int i = blockIdx.x * TB + threadIdx.x;
    float xi = x[i], yi = y[i];

    int j0 = blockIdx.y * JT;
    for (int t = threadIdx.x; t < JT; t += TB) {
        int j = j0 + t;
        sx[t] = x[j]; sy[t] = y[j]; sw[t] = g_w[j];
    }
    __syncthreads();

    float sa = 0.0f, sb = 0.0f;
    #pragma unroll 8
    for (int t = 0; t < JT; ++t) {
        float wj = sw[t];
        sa = fmaf(fabsf(xi - sx[t]), wj, sa);
        sb = fmaf(fabsf(yi - sy[t]), wj, sb);
    }
    atomicAdd(&g_asum[i], sa);
    atomicAdd(&g_bsum[i], sb);
}

// ---------------------------------------------------------------------------
// Kernel B2 (1 block): a0 = sum(asum*w)/N^2, b0 likewise.
// ---------------------------------------------------------------------------
__global__ void kB2(int n) {
    float sa = 0.0f, sb = 0.0f;
    for (int i = threadIdx.x; i < n; i += blockDim.x) {
        float w = g_w[i];
        sa = fmaf(g_asum[i], w, sa);
        sb = fmaf(g_bsum[i], w, sb);
    }
    sa = blockReduceSum(sa);
    sb = blockReduceSum(sb);
    if (threadIdx.x == 0) {
        float inv = 1.0f / ((float)n * (float)n);
        g_a0 = sa * inv;
        g_b0 = sb * inv;
    }
}

// ---------------------------------------------------------------------------
// Kernel C: pass 2, S_AB/S_AA/S_BB.  grid (n/(CT*ITEMS), n/CJT), CT threads.
// ---------------------------------------------------------------------------
#define CT 256
#define ITEMS 4
#define CJT 256
__global__ void kC(const float* __restrict__ x, const float* __restrict__ y, int n) {
    __shared__ float sx[CJT], sy[CJT], sw[CJT], sal[CJT], sbe[CJT];
    int tid = threadIdx.x;
    float invn = 1.0f / (float)n;
    float a0 = g_a0, b0 = g_b0;

    float xi[ITEMS], yi[ITEMS], ca[ITEMS], cb[ITEMS], wi[ITEMS];
    int ibase = blockIdx.x * (CT * ITEMS) + tid;
    #pragma unroll
    for (int k = 0; k < ITEMS; ++k) {
        int i = ibase + k * CT;
        xi[k] = x[i]; yi[k] = y[i]; wi[k] = g_w[i];
        ca[k] = a0 - g_asum[i] * invn;
        cb[k] = b0 - g_bsum[i] * invn;
    }

    {
        int j = blockIdx.y * CJT + tid;
        sx[tid]  = x[j];
        sy[tid]  = y[j];
        sw[tid]  = g_w[j];
        sal[tid] = g_asum[j] * invn;
        sbe[tid] = g_bsum[j] * invn;
    }
    __syncthreads();

    float sab[ITEMS], saa[ITEMS], sbb[ITEMS];
    #pragma unroll
    for (int k = 0; k < ITEMS; ++k) { sab[k] = 0.0f; saa[k] = 0.0f; sbb[k] = 0.0f; }

    #pragma unroll 4
    for (int t = 0; t < CJT; ++t) {
        float xj = sx[t], yj = sy[t], wj = sw[t];
        float aj = sal[t], bj = sbe[t];
        #pragma unroll
        for (int k = 0; k < ITEMS; ++k) {
            float a = fabsf(xi[k] - xj) - aj + ca[k];
            float b = fabsf(yi[k] - yj) - bj + cb[k];
            float aw = a * wj;
            float bw = b * wj;
            sab[k] = fmaf(aw, b, sab[k]);
            saa[k] = fmaf(aw, a, saa[k]);
            sbb[k] = fmaf(bw, b, sbb[k]);
        }
    }

    float pab = 0.0f, paa = 0.0f, pbb = 0.0f;
    #pragma unroll
    for (int k = 0; k < ITEMS; ++k) {
        pab = fmaf(wi[k], sab[k], pab);
        paa = fmaf(wi[k], saa[k], paa);
        pbb = fmaf(wi[k], sbb[k], pbb);
    }
    pab = blockReduceSum(pab);
    paa = blockReduceSum(paa);
    pbb = blockReduceSum(pbb);
    if (tid == 0) {
        atomicAdd(&g_sab, pab);
        atomicAdd(&g_saa, paa);
        atomicAdd(&g_sbb, pbb);
    }
}

// ---------------------------------------------------------------------------
// Kernel D: finalize outputs [bce, disco, tot].
// ---------------------------------------------------------------------------
__global__ void kD(float* __restrict__ out, int out_size) {
    float bce   = g_bce;
    float disco = g_sab / sqrtf(g_saa * g_sbb);
    float vals[3];
    vals[0] = bce;
    vals[1] = disco;
    vals[2] = bce + 0.1f * disco;
    int m = out_size < 3 ? out_size : 3;
    for (int i = 0; i < m; ++i) out[i] = vals[i];
    for (int i = 3; i < out_size; ++i) out[i] = 0.0f;
}

// ---------------------------------------------------------------------------
extern "C" void kernel_launch(void* const* d_in, const int* in_sizes, int n_in,
                              void* d_out, int out_size) {
    const float* outputs = (const float*)d_in[0];
    const float* labels  = (const float*)d_in[1];
    const float* event   = (const float*)d_in[2];
    const float* weights = (const float*)d_in[3];
    int n = in_sizes[0];

    kA<<<1, 1024>>>(outputs, labels, weights, n);

    dim3 gb(n / TB, n / JT);
    kB<<<gb, TB>>>(outputs, event, n);

    kB2<<<1, 1024>>>(n);

    dim3 gc(n / (CT * ITEMS), n / CJT);
    kC<<<gc, CT>>>(outputs, event, n);

    kD<<<1, 1>>>((float*)d_out, out_size);
}